// round 2
// baseline (speedup 1.0000x reference)
#include <cuda_runtime.h>
#include <math.h>
#include <stdint.h>

// ---------------- problem constants ----------------
#define T_STEPS 64
#define B_SZ    512
#define OBS_    1536
#define ACT_    32
#define D_      2048
#define H_      2048
#define K_      32
#define V_      32
#define S_      1024   // K_*V_

// ---------------- device scratch ----------------
__device__ float g_obs_e[(size_t)T_STEPS * B_SZ * H_];
__device__ float g_act_e[(size_t)T_STEPS * B_SZ * H_];
__device__ float g_x[(size_t)B_SZ * H_];
__device__ float g_parts[(size_t)B_SZ * 3 * D_];
__device__ float g_h[(size_t)B_SZ * H_];
__device__ float g_deter[(size_t)B_SZ * D_];
__device__ int   g_idx[B_SZ * K_];

// ---------------- helpers ----------------
__device__ __forceinline__ void cp_async16(void* smem_dst, const void* gmem_src) {
    unsigned s = (unsigned)__cvta_generic_to_shared(smem_dst);
    asm volatile("cp.async.ca.shared.global [%0], [%1], 16;\n" :: "r"(s), "l"(gmem_src));
}
__device__ __forceinline__ void cp_async_commit() {
    asm volatile("cp.async.commit_group;\n" ::: "memory");
}
__device__ __forceinline__ void cp_async_wait_all() {
    asm volatile("cp.async.wait_group 0;\n" ::: "memory");
}
__device__ __forceinline__ void ffma2(unsigned long long& acc,
                                      unsigned long long a,
                                      unsigned long long b) {
    asm volatile("fma.rn.f32x2 %0, %1, %2, %0;\n" : "+l"(acc) : "l"(a), "l"(b));
}
__device__ __forceinline__ float2 ull2f2(unsigned long long v) {
    float2 r;
    r.x = __uint_as_float((unsigned)(v & 0xffffffffull));
    r.y = __uint_as_float((unsigned)(v >> 32));
    return r;
}

// ---------------- fp32 SGEMM, f32x2 packed FMA, cp.async B, dup-A smem ----------------
// EPI: 0=none, 1=+bias, 2=+bias,ELU, 3=+bias,+addmat,ELU
template<int BM, int BN, int BK, int TM, int TN, bool CONCAT, int EPI>
__global__ void __launch_bounds__(256, 2)
sgemm2_kernel(const float* __restrict__ A, const float* __restrict__ A2,
              const float* __restrict__ B, float* __restrict__ C,
              const float* __restrict__ bias, const float* __restrict__ addm,
              int M, int N, int K, int K1)
{
    constexpr int THREADS = (BM/TM)*(BN/TN);
    static_assert(THREADS == 256, "expect 256 threads");
    constexpr int AROW = 2*BM + 4;          // duplicated A row, 16B-aligned stride
    extern __shared__ __align__(16) float smem[];
    float* As = smem;                        // [2][BK][AROW]
    float* Bs = smem + 2*BK*AROW;            // [2][BK][BN]

    const int tid = threadIdx.x;
    const int tx  = tid % (BN/TN);
    const int ty  = tid / (BN/TN);
    const int bm  = blockIdx.y * BM;
    const int bn  = blockIdx.x * BN;

    constexpr int A_TPR = BK / 4;            // threads per A row (float4)
    constexpr int A_RS  = THREADS / A_TPR;
    constexpr int A_IT  = BM / A_RS;
    const int a_r = tid / A_TPR;
    const int a_c = (tid % A_TPR) * 4;

    constexpr int B_TPR = BN / 4;
    constexpr int B_RS  = THREADS / B_TPR;
    constexpr int B_IT  = BK / B_RS;
    const int b_r = tid / B_TPR;
    const int b_c = (tid % B_TPR) * 4;

    float4 ar[A_IT];

    unsigned long long acc[TM][TN/2];
    #pragma unroll
    for (int i = 0; i < TM; ++i)
        #pragma unroll
        for (int j = 0; j < TN/2; ++j) acc[i][j] = 0ull;

    auto a_gload = [&](int kt) {
        const int k0 = kt * BK;
        #pragma unroll
        for (int i = 0; i < A_IT; ++i) {
            int gr = bm + a_r + i * A_RS;
            int gk = k0 + a_c;
            const float* src;
            if (CONCAT) {
                src = (gk < K1) ? (A  + (size_t)gr * K1       + gk)
                                : (A2 + (size_t)gr * (K - K1) + (gk - K1));
            } else {
                src = A + (size_t)gr * K + gk;
            }
            ar[i] = *(const float4*)src;
        }
    };
    auto a_sstore = [&](int bf) {
        #pragma unroll
        for (int i = 0; i < A_IT; ++i) {
            int r2 = 2 * (a_r + i * A_RS);
            float* base = As + (size_t)bf * BK * AROW;
            *(float2*)(base + (a_c + 0) * AROW + r2) = make_float2(ar[i].x, ar[i].x);
            *(float2*)(base + (a_c + 1) * AROW + r2) = make_float2(ar[i].y, ar[i].y);
            *(float2*)(base + (a_c + 2) * AROW + r2) = make_float2(ar[i].z, ar[i].z);
            *(float2*)(base + (a_c + 3) * AROW + r2) = make_float2(ar[i].w, ar[i].w);
        }
    };
    auto b_gload = [&](int kt, int bf) {
        const int k0 = kt * BK;
        float* base = Bs + (size_t)bf * BK * BN;
        #pragma unroll
        for (int i = 0; i < B_IT; ++i) {
            int r = b_r + i * B_RS;
            cp_async16(base + r * BN + b_c, B + (size_t)(k0 + r) * N + bn + b_c);
        }
        cp_async_commit();
    };

    const int ntiles = K / BK;
    // prologue
    b_gload(0, 0);
    a_gload(0);
    a_sstore(0);
    cp_async_wait_all();
    __syncthreads();

    int buf = 0;
    for (int kt = 0; kt < ntiles; ++kt) {
        if (kt + 1 < ntiles) {
            b_gload(kt + 1, buf ^ 1);   // async, overlaps compute
            a_gload(kt + 1);            // into regs, overlaps compute
        }
        const float* Asb = As + (size_t)buf * BK * AROW;
        const float* Bsb = Bs + (size_t)buf * BK * BN;
        #pragma unroll
        for (int kk = 0; kk < BK; ++kk) {
            unsigned long long a_dup[TM];
            #pragma unroll
            for (int i2 = 0; i2 < TM/2; ++i2) {
                ulonglong2 t = *(const ulonglong2*)(Asb + kk * AROW + 2 * ty * TM + 4 * i2);
                a_dup[2*i2]     = t.x;
                a_dup[2*i2 + 1] = t.y;
            }
            unsigned long long b2[TN/2];
            #pragma unroll
            for (int j2 = 0; j2 < TN/4; ++j2) {
                ulonglong2 u = *(const ulonglong2*)(Bsb + kk * BN + tx * TN + 4 * j2);
                b2[2*j2]     = u.x;
                b2[2*j2 + 1] = u.y;
            }
            #pragma unroll
            for (int i = 0; i < TM; ++i)
                #pragma unroll
                for (int j = 0; j < TN/2; ++j)
                    ffma2(acc[i][j], a_dup[i], b2[j]);
        }
        if (kt + 1 < ntiles) {
            a_sstore(buf ^ 1);
            cp_async_wait_all();
        }
        __syncthreads();
        buf ^= 1;
    }

    #pragma unroll
    for (int i = 0; i < TM; ++i) {
        int row = bm + ty * TM + i;
        #pragma unroll
        for (int j2 = 0; j2 < TN/2; ++j2) {
            int col = bn + tx * TN + 2 * j2;
            float2 v = ull2f2(acc[i][j2]);
            if (EPI >= 1) { v.x += bias[col]; v.y += bias[col + 1]; }
            if (EPI == 3) {
                float2 am = *(const float2*)(addm + (size_t)row * N + col);
                v.x += am.x; v.y += am.y;
            }
            if (EPI >= 2) {
                v.x = (v.x > 0.f) ? v.x : expm1f(v.x);
                v.y = (v.y > 0.f) ? v.y : expm1f(v.y);
            }
            *(float2*)(C + (size_t)row * N + col) = v;
        }
    }
}

// ---------------- x = elu(act_e[t] + b_is + sum of one-hot-selected W_is rows) ----------------
__global__ void x_gather_kernel(const float* __restrict__ ae,
                                const float* __restrict__ b_is,
                                const float* __restrict__ W_is,
                                const int* __restrict__ idx,
                                float* __restrict__ x)
{
    int j = blockIdx.x * blockDim.x + threadIdx.x;
    int b = blockIdx.y;
    __shared__ int sid[K_];
    if (threadIdx.x < K_) sid[threadIdx.x] = idx[b * K_ + threadIdx.x];
    __syncthreads();
    float v = ae[(size_t)b * H_ + j] + b_is[j];
    #pragma unroll
    for (int k = 0; k < K_; ++k)
        v += W_is[(size_t)sid[k] * H_ + j];
    x[(size_t)b * H_ + j] = (v > 0.f) ? v : expm1f(v);
}

// ---------------- fused LayerNorm(6144) + GRU gates + deter update ----------------
__global__ void ln_gru_kernel(const float* __restrict__ parts,
                              const float* __restrict__ ln_g,
                              const float* __restrict__ ln_b,
                              float* __restrict__ deter,
                              float* __restrict__ deters_out)
{
    const int row = blockIdx.x;
    const float* p = parts + (size_t)row * (3 * D_);
    float s = 0.f, s2 = 0.f;
    for (int i = threadIdx.x * 4; i < 3 * D_; i += 256 * 4) {
        float4 v = *(const float4*)(p + i);
        s  += v.x + v.y + v.z + v.w;
        s2 += v.x * v.x + v.y * v.y + v.z * v.z + v.w * v.w;
    }
    __shared__ float shs[8], shs2[8];
    #pragma unroll
    for (int off = 16; off > 0; off >>= 1) {
        s  += __shfl_down_sync(0xffffffffu, s,  off);
        s2 += __shfl_down_sync(0xffffffffu, s2, off);
    }
    int warp = threadIdx.x >> 5, lane = threadIdx.x & 31;
    if (lane == 0) { shs[warp] = s; shs2[warp] = s2; }
    __syncthreads();
    __shared__ float sh_m, sh_rstd;
    if (threadIdx.x == 0) {
        float S = 0.f, S2 = 0.f;
        #pragma unroll
        for (int i = 0; i < 8; ++i) { S += shs[i]; S2 += shs2[i]; }
        float m   = S * (1.f / (3 * D_));
        float var = S2 * (1.f / (3 * D_)) - m * m;
        sh_m = m; sh_rstd = rsqrtf(var + 1e-5f);
    }
    __syncthreads();
    const float m = sh_m, rstd = sh_rstd;
    for (int j = threadIdx.x; j < D_; j += 256) {
        float r = (p[j]          - m) * rstd * ln_g[j]          + ln_b[j];
        float c = (p[j + D_]     - m) * rstd * ln_g[j + D_]     + ln_b[j + D_];
        float u = (p[j + 2 * D_] - m) * rstd * ln_g[j + 2 * D_] + ln_b[j + 2 * D_];
        float sr   = 1.f / (1.f + expf(-r));
        float cand = tanhf(sr * c);
        float up   = 1.f / (1.f + expf(-(u - 1.f)));
        float dprev = deter[(size_t)row * D_ + j];
        float dn = up * cand + (1.f - up) * dprev;
        deter[(size_t)row * D_ + j] = dn;
        deters_out[(size_t)row * D_ + j] = dn;
    }
}

// ---------------- gumbel-max sampling: one warp per (b,k) ----------------
__global__ void sample_kernel(const float* __restrict__ logits,
                              const float* __restrict__ unif,
                              int* __restrict__ idx_out,
                              float* __restrict__ stochs_out)
{
    int gw   = (blockIdx.x * blockDim.x + threadIdx.x) >> 5;
    int lane = threadIdx.x & 31;
    size_t base = (size_t)gw * V_ + lane;
    float logit = logits[base];
    float u = unif[base];
    u = fminf(fmaxf(u, 1e-5f), 1.0f - 1e-5f);
    float val = logit - logf(-logf(u));
    int idx = lane;
    #pragma unroll
    for (int off = 16; off > 0; off >>= 1) {
        float ov = __shfl_down_sync(0xffffffffu, val, off);
        int   oi = __shfl_down_sync(0xffffffffu, idx, off);
        if (ov > val || (ov == val && oi < idx)) { val = ov; idx = oi; }
    }
    idx = __shfl_sync(0xffffffffu, idx, 0);
    stochs_out[base] = (lane == idx) ? 1.0f : 0.0f;
    if (lane == 0) idx_out[gw] = ((gw & (K_ - 1)) << 5) | idx;
}

// ---------------- launch helpers ----------------
template<int BM, int BN, int BK, int TM, int TN, bool CONCAT, int EPI>
static void launch_sgemm2(const float* A, const float* A2, const float* B, float* C,
                          const float* bias, const float* addm,
                          int M, int N, int K, int K1)
{
    constexpr int AROW = 2*BM + 4;
    constexpr size_t SMEM = (size_t)(2*BK*AROW + 2*BK*BN) * sizeof(float);
    static bool attr_set = false;
    if (!attr_set) {
        cudaFuncSetAttribute((const void*)sgemm2_kernel<BM,BN,BK,TM,TN,CONCAT,EPI>,
                             cudaFuncAttributeMaxDynamicSharedMemorySize, (int)SMEM);
        attr_set = true;
    }
    dim3 g(N / BN, M / BM);
    sgemm2_kernel<BM,BN,BK,TM,TN,CONCAT,EPI><<<g, 256, SMEM>>>(
        A, A2, B, C, bias, addm, M, N, K, K1);
}

// ---------------- host orchestration ----------------
extern "C" void kernel_launch(void* const* d_in, const int* in_sizes, int n_in,
                              void* d_out, int out_size)
{
    (void)in_sizes; (void)n_in; (void)out_size;
    const float* obs    = (const float*)d_in[0];
    const float* act    = (const float*)d_in[1];
    const float* deter0 = (const float*)d_in[2];
    const float* stoch0 = (const float*)d_in[3];
    const float* unif   = (const float*)d_in[4];
    const float* W_oo   = (const float*)d_in[5];
    const float* b_oo   = (const float*)d_in[6];
    const float* W_ia   = (const float*)d_in[7];
    const float* b_ia   = (const float*)d_in[8];
    const float* W_is   = (const float*)d_in[9];
    const float* b_is   = (const float*)d_in[10];
    const float* W_gru  = (const float*)d_in[11];
    const float* ln_g   = (const float*)d_in[12];
    const float* ln_b   = (const float*)d_in[13];
    const float* W_od   = (const float*)d_in[14];
    const float* b_od   = (const float*)d_in[15];
    const float* W_op   = (const float*)d_in[16];
    const float* b_op   = (const float*)d_in[17];
    const float* W_io   = (const float*)d_in[18];
    const float* b_io   = (const float*)d_in[19];
    const float* W_ip   = (const float*)d_in[20];
    const float* b_ip   = (const float*)d_in[21];

    float* out    = (float*)d_out;
    float* deters = out;
    float* stochs = deters + (size_t)T_STEPS * B_SZ * D_;
    float* posts  = stochs + (size_t)T_STEPS * B_SZ * S_;
    float* priors = posts  + (size_t)T_STEPS * B_SZ * S_;

    float *obs_e, *act_e, *xbuf, *parts, *hbuf, *deter; int* idxb;
    cudaGetSymbolAddress((void**)&obs_e, g_obs_e);
    cudaGetSymbolAddress((void**)&act_e, g_act_e);
    cudaGetSymbolAddress((void**)&xbuf,  g_x);
    cudaGetSymbolAddress((void**)&parts, g_parts);
    cudaGetSymbolAddress((void**)&hbuf,  g_h);
    cudaGetSymbolAddress((void**)&deter, g_deter);
    cudaGetSymbolAddress((void**)&idxb,  g_idx);

    cudaMemcpyAsync(deter, deter0, (size_t)B_SZ * D_ * sizeof(float),
                    cudaMemcpyDeviceToDevice, 0);

    // obs_e = obs @ W_oo + b_oo
    launch_sgemm2<128,128,16,8,8,false,1>(obs, nullptr, W_oo, obs_e, b_oo, nullptr,
                                          T_STEPS * B_SZ, H_, OBS_, 0);
    // act_e = act @ W_ia + b_ia
    launch_sgemm2<128,128,16,8,8,false,1>(act, nullptr, W_ia, act_e, b_ia, nullptr,
                                          T_STEPS * B_SZ, H_, ACT_, 0);

    for (int t = 0; t < T_STEPS; ++t) {
        const float* ae = act_e + (size_t)t * B_SZ * H_;
        const float* oe = obs_e + (size_t)t * B_SZ * H_;

        // x = elu(act_e[t] + stoch @ W_is + b_is)
        if (t == 0) {
            launch_sgemm2<64,128,16,4,8,false,3>(stoch0, nullptr, W_is, xbuf, b_is, ae,
                                                 B_SZ, H_, S_, 0);
        } else {
            dim3 g(H_ / 256, B_SZ);
            x_gather_kernel<<<g, 256>>>(ae, b_is, W_is, idxb, xbuf);
        }
        // parts = [x | deter] @ W_gru
        launch_sgemm2<128,128,16,8,8,true,0>(xbuf, deter, W_gru, parts, nullptr, nullptr,
                                             B_SZ, 3 * D_, H_ + D_, H_);
        // layernorm + gates + deter update
        ln_gru_kernel<<<B_SZ, 256>>>(parts, ln_g, ln_b, deter,
                                     deters + (size_t)t * B_SZ * D_);
        // h = elu(deter @ W_od + b_od + obs_e[t])
        launch_sgemm2<64,64,16,4,4,false,3>(deter, nullptr, W_od, hbuf, b_od, oe,
                                            B_SZ, H_, D_, 0);
        // posts[t] = h @ W_op + b_op
        launch_sgemm2<64,64,16,4,4,false,1>(hbuf, nullptr, W_op,
                                            posts + (size_t)t * B_SZ * S_, b_op, nullptr,
                                            B_SZ, S_, H_, 0);
        // gumbel-max sample
        sample_kernel<<<(B_SZ * K_ * 32) / 256, 256>>>(
            posts + (size_t)t * B_SZ * S_,
            unif + (size_t)t * B_SZ * K_ * V_,
            idxb,
            stochs + (size_t)t * B_SZ * S_);
    }

    // priors = (elu(deters @ W_io + b_io)) @ W_ip + b_ip
    launch_sgemm2<128,128,16,8,8,false,2>(deters, nullptr, W_io, act_e, b_io, nullptr,
                                          T_STEPS * B_SZ, H_, D_, 0);
    launch_sgemm2<128,128,16,8,8,false,1>(act_e, nullptr, W_ip, priors, b_ip, nullptr,
                                          T_STEPS * B_SZ, S_, H_, 0);
}

// round 3
// speedup vs baseline: 1.1657x; 1.1657x over previous
#include <cuda_runtime.h>
#include <math.h>
#include <stdint.h>

// ---------------- problem constants ----------------
#define T_STEPS 64
#define B_SZ    512
#define OBS_    1536
#define ACT_    32
#define D_      2048
#define H_      2048
#define K_      32
#define V_      32
#define S_      1024   // K_*V_

// ---------------- device scratch ----------------
__device__ float g_obs_e[(size_t)T_STEPS * B_SZ * H_];
__device__ float g_act_e[(size_t)T_STEPS * B_SZ * H_];
__device__ float g_x[(size_t)B_SZ * H_];
__device__ float g_parts[(size_t)B_SZ * 3 * D_];
__device__ float g_h[(size_t)B_SZ * H_];
__device__ float g_deter[(size_t)B_SZ * D_];
__device__ int   g_idx[B_SZ * K_];

// ---------------- helpers ----------------
__device__ __forceinline__ void cp_async16(void* smem_dst, const void* gmem_src) {
    unsigned s = (unsigned)__cvta_generic_to_shared(smem_dst);
    asm volatile("cp.async.ca.shared.global [%0], [%1], 16;\n" :: "r"(s), "l"(gmem_src));
}
__device__ __forceinline__ void cp_async_commit() {
    asm volatile("cp.async.commit_group;\n" ::: "memory");
}
__device__ __forceinline__ void cp_async_wait_all() {
    asm volatile("cp.async.wait_group 0;\n" ::: "memory");
}
__device__ __forceinline__ void ffma2(unsigned long long& acc,
                                      unsigned long long a,
                                      unsigned long long b) {
    asm volatile("fma.rn.f32x2 %0, %1, %2, %0;\n" : "+l"(acc) : "l"(a), "l"(b));
}
__device__ __forceinline__ unsigned long long dup_f32(float b) {
    unsigned long long u;
    asm("mov.b64 %0, {%1, %1};\n" : "=l"(u) : "f"(b));
    return u;
}
__device__ __forceinline__ float2 ull2f2(unsigned long long v) {
    float2 r;
    r.x = __uint_as_float((unsigned)(v & 0xffffffffull));
    r.y = __uint_as_float((unsigned)(v >> 32));
    return r;
}

// ---------------- fp32 SGEMM: f32x2 FMA with M-paired A (no smem duplication) -------
// A operand pairs come straight out of LDS.128 of As[k][m] (consecutive m).
// B operand duplicated {b,b} in registers via mov.b64 (alu pipe).
// EPI: 0=none, 1=+bias, 2=+bias,ELU, 3=+bias,+addmat,ELU
template<int BM, int BN, int BK, int TM, int TN, bool CONCAT, int EPI>
__global__ void __launch_bounds__(256, 2)
sgemm3_kernel(const float* __restrict__ A, const float* __restrict__ A2,
              const float* __restrict__ B, float* __restrict__ C,
              const float* __restrict__ bias, const float* __restrict__ addm,
              int M, int N, int K, int K1)
{
    constexpr int THREADS = (BM/TM)*(BN/TN);
    static_assert(THREADS == 256, "expect 256 threads");
    static_assert(TM % 4 == 0 || TM == 4, "TM multiple of 4");
    constexpr int AROW = BM + 4;             // 16B-aligned row stride
    extern __shared__ __align__(16) float smem[];
    float* As = smem;                        // [2][BK][AROW]
    float* Bs = smem + 2*BK*AROW;            // [2][BK][BN]

    const int tid = threadIdx.x;
    const int tx  = tid % (BN/TN);
    const int ty  = tid / (BN/TN);
    const int bm  = blockIdx.y * BM;
    const int bn  = blockIdx.x * BN;

    constexpr int A_TPR = BK / 4;            // threads per A row (float4 along K)
    constexpr int A_RS  = THREADS / A_TPR;
    constexpr int A_IT  = BM / A_RS;
    const int a_r = tid / A_TPR;
    const int a_c = (tid % A_TPR) * 4;

    constexpr int B_TPR = BN / 4;
    constexpr int B_RS  = THREADS / B_TPR;
    constexpr int B_IT  = BK / B_RS;
    const int b_r = tid / B_TPR;
    const int b_c = (tid % B_TPR) * 4;

    float4 ar[A_IT];

    unsigned long long acc[TM/2][TN];        // pair along M: {row 2i, row 2i+1}
    #pragma unroll
    for (int i = 0; i < TM/2; ++i)
        #pragma unroll
        for (int j = 0; j < TN; ++j) acc[i][j] = 0ull;

    auto a_gload = [&](int kt) {
        const int k0 = kt * BK;
        #pragma unroll
        for (int i = 0; i < A_IT; ++i) {
            int gr = bm + a_r + i * A_RS;
            int gk = k0 + a_c;
            const float* src;
            if (CONCAT) {
                src = (gk < K1) ? (A  + (size_t)gr * K1       + gk)
                                : (A2 + (size_t)gr * (K - K1) + (gk - K1));
            } else {
                src = A + (size_t)gr * K + gk;
            }
            ar[i] = *(const float4*)src;
        }
    };
    auto a_sstore = [&](int bf) {
        float* base = As + (size_t)bf * BK * AROW;
        #pragma unroll
        for (int i = 0; i < A_IT; ++i) {
            int r = a_r + i * A_RS;
            base[(a_c + 0) * AROW + r] = ar[i].x;
            base[(a_c + 1) * AROW + r] = ar[i].y;
            base[(a_c + 2) * AROW + r] = ar[i].z;
            base[(a_c + 3) * AROW + r] = ar[i].w;
        }
    };
    auto b_gload = [&](int kt, int bf) {
        const int k0 = kt * BK;
        float* base = Bs + (size_t)bf * BK * BN;
        #pragma unroll
        for (int i = 0; i < B_IT; ++i) {
            int r = b_r + i * B_RS;
            cp_async16(base + r * BN + b_c, B + (size_t)(k0 + r) * N + bn + b_c);
        }
        cp_async_commit();
    };

    const int ntiles = K / BK;
    b_gload(0, 0);
    a_gload(0);
    a_sstore(0);
    cp_async_wait_all();
    __syncthreads();

    int buf = 0;
    for (int kt = 0; kt < ntiles; ++kt) {
        if (kt + 1 < ntiles) {
            b_gload(kt + 1, buf ^ 1);
            a_gload(kt + 1);
        }
        const float* Asb = As + (size_t)buf * BK * AROW;
        const float* Bsb = Bs + (size_t)buf * BK * BN;
        #pragma unroll
        for (int kk = 0; kk < BK; ++kk) {
            // A: LDS.128 -> two natural M-pairs each
            unsigned long long apair[TM/2];
            #pragma unroll
            for (int i4 = 0; i4 < TM/4; ++i4) {
                ulonglong2 p = *(const ulonglong2*)(Asb + kk * AROW + ty * TM + 4 * i4);
                apair[2*i4]     = p.x;
                apair[2*i4 + 1] = p.y;
            }
            // B: LDS.128 scalar, duplicate in registers (alu pipe)
            unsigned long long bdup[TN];
            #pragma unroll
            for (int j4 = 0; j4 < TN/4; ++j4) {
                float4 bv = *(const float4*)(Bsb + kk * BN + tx * TN + 4 * j4);
                bdup[4*j4 + 0] = dup_f32(bv.x);
                bdup[4*j4 + 1] = dup_f32(bv.y);
                bdup[4*j4 + 2] = dup_f32(bv.z);
                bdup[4*j4 + 3] = dup_f32(bv.w);
            }
            #pragma unroll
            for (int i = 0; i < TM/2; ++i)
                #pragma unroll
                for (int j = 0; j < TN; ++j)
                    ffma2(acc[i][j], apair[i], bdup[j]);
        }
        if (kt + 1 < ntiles) {
            a_sstore(buf ^ 1);
            cp_async_wait_all();
        }
        __syncthreads();
        buf ^= 1;
    }

    // epilogue: reassemble per-row vectors, vectorized float4 stores
    #pragma unroll
    for (int i2 = 0; i2 < TM/2; ++i2) {
        int row0 = bm + ty * TM + 2 * i2;
        float lo[TN], hi[TN];
        #pragma unroll
        for (int j = 0; j < TN; ++j) {
            float2 v = ull2f2(acc[i2][j]);
            lo[j] = v.x; hi[j] = v.y;
        }
        #pragma unroll
        for (int half = 0; half < 2; ++half) {
            int row = row0 + half;
            float* vals = half ? hi : lo;
            #pragma unroll
            for (int j = 0; j < TN; ++j) {
                int col = bn + tx * TN + j;
                float v = vals[j];
                if (EPI >= 1) v += bias[col];
                if (EPI == 3) v += addm[(size_t)row * N + col];
                if (EPI >= 2) v = (v > 0.f) ? v : expm1f(v);
                vals[j] = v;
            }
            #pragma unroll
            for (int j4 = 0; j4 < TN/4; ++j4)
                *(float4*)(C + (size_t)row * N + bn + tx * TN + 4 * j4) =
                    *(const float4*)(vals + 4 * j4);
        }
    }
}

// ---------------- x = elu(act_e[t] + b_is + sum of one-hot-selected W_is rows) -----
__global__ void x_gather_kernel(const float* __restrict__ ae,
                                const float* __restrict__ b_is,
                                const float* __restrict__ W_is,
                                const int* __restrict__ idx,
                                float* __restrict__ x)
{
    int j = blockIdx.x * blockDim.x + threadIdx.x;
    int b = blockIdx.y;
    __shared__ int sid[K_];
    if (threadIdx.x < K_) sid[threadIdx.x] = idx[b * K_ + threadIdx.x];
    __syncthreads();
    float v = ae[(size_t)b * H_ + j] + b_is[j];
    #pragma unroll
    for (int k = 0; k < K_; ++k)
        v += W_is[(size_t)sid[k] * H_ + j];
    x[(size_t)b * H_ + j] = (v > 0.f) ? v : expm1f(v);
}

// ---------------- fused LayerNorm(6144) + GRU gates + deter update ----------------
__global__ void ln_gru_kernel(const float* __restrict__ parts,
                              const float* __restrict__ ln_g,
                              const float* __restrict__ ln_b,
                              float* __restrict__ deter,
                              float* __restrict__ deters_out)
{
    const int row = blockIdx.x;
    const float* p = parts + (size_t)row * (3 * D_);
    float s = 0.f, s2 = 0.f;
    for (int i = threadIdx.x * 4; i < 3 * D_; i += 256 * 4) {
        float4 v = *(const float4*)(p + i);
        s  += v.x + v.y + v.z + v.w;
        s2 += v.x * v.x + v.y * v.y + v.z * v.z + v.w * v.w;
    }
    __shared__ float shs[8], shs2[8];
    #pragma unroll
    for (int off = 16; off > 0; off >>= 1) {
        s  += __shfl_down_sync(0xffffffffu, s,  off);
        s2 += __shfl_down_sync(0xffffffffu, s2, off);
    }
    int warp = threadIdx.x >> 5, lane = threadIdx.x & 31;
    if (lane == 0) { shs[warp] = s; shs2[warp] = s2; }
    __syncthreads();
    __shared__ float sh_m, sh_rstd;
    if (threadIdx.x == 0) {
        float S = 0.f, S2 = 0.f;
        #pragma unroll
        for (int i = 0; i < 8; ++i) { S += shs[i]; S2 += shs2[i]; }
        float m   = S * (1.f / (3 * D_));
        float var = S2 * (1.f / (3 * D_)) - m * m;
        sh_m = m; sh_rstd = rsqrtf(var + 1e-5f);
    }
    __syncthreads();
    const float m = sh_m, rstd = sh_rstd;
    for (int j = threadIdx.x; j < D_; j += 256) {
        float r = (p[j]          - m) * rstd * ln_g[j]          + ln_b[j];
        float c = (p[j + D_]     - m) * rstd * ln_g[j + D_]     + ln_b[j + D_];
        float u = (p[j + 2 * D_] - m) * rstd * ln_g[j + 2 * D_] + ln_b[j + 2 * D_];
        float sr   = 1.f / (1.f + expf(-r));
        float cand = tanhf(sr * c);
        float up   = 1.f / (1.f + expf(-(u - 1.f)));
        float dprev = deter[(size_t)row * D_ + j];
        float dn = up * cand + (1.f - up) * dprev;
        deter[(size_t)row * D_ + j] = dn;
        deters_out[(size_t)row * D_ + j] = dn;
    }
}

// ---------------- gumbel-max sampling: one warp per (b,k) ----------------
__global__ void sample_kernel(const float* __restrict__ logits,
                              const float* __restrict__ unif,
                              int* __restrict__ idx_out,
                              float* __restrict__ stochs_out)
{
    int gw   = (blockIdx.x * blockDim.x + threadIdx.x) >> 5;
    int lane = threadIdx.x & 31;
    size_t base = (size_t)gw * V_ + lane;
    float logit = logits[base];
    float u = unif[base];
    u = fminf(fmaxf(u, 1e-5f), 1.0f - 1e-5f);
    float val = logit - logf(-logf(u));
    int idx = lane;
    #pragma unroll
    for (int off = 16; off > 0; off >>= 1) {
        float ov = __shfl_down_sync(0xffffffffu, val, off);
        int   oi = __shfl_down_sync(0xffffffffu, idx, off);
        if (ov > val || (ov == val && oi < idx)) { val = ov; idx = oi; }
    }
    idx = __shfl_sync(0xffffffffu, idx, 0);
    stochs_out[base] = (lane == idx) ? 1.0f : 0.0f;
    if (lane == 0) idx_out[gw] = ((gw & (K_ - 1)) << 5) | idx;
}

// ---------------- launch helper ----------------
template<int BM, int BN, int BK, int TM, int TN, bool CONCAT, int EPI>
static void launch_sgemm3(const float* A, const float* A2, const float* B, float* C,
                          const float* bias, const float* addm,
                          int M, int N, int K, int K1)
{
    constexpr int AROW = BM + 4;
    constexpr size_t SMEM = (size_t)(2*BK*AROW + 2*BK*BN) * sizeof(float);
    static bool attr_set = false;
    if (!attr_set) {
        cudaFuncSetAttribute((const void*)sgemm3_kernel<BM,BN,BK,TM,TN,CONCAT,EPI>,
                             cudaFuncAttributeMaxDynamicSharedMemorySize, (int)SMEM);
        attr_set = true;
    }
    dim3 g(N / BN, M / BM);
    sgemm3_kernel<BM,BN,BK,TM,TN,CONCAT,EPI><<<g, 256, SMEM>>>(
        A, A2, B, C, bias, addm, M, N, K, K1);
}

// ---------------- host orchestration ----------------
extern "C" void kernel_launch(void* const* d_in, const int* in_sizes, int n_in,
                              void* d_out, int out_size)
{
    (void)in_sizes; (void)n_in; (void)out_size;
    const float* obs    = (const float*)d_in[0];
    const float* act    = (const float*)d_in[1];
    const float* deter0 = (const float*)d_in[2];
    const float* stoch0 = (const float*)d_in[3];
    const float* unif   = (const float*)d_in[4];
    const float* W_oo   = (const float*)d_in[5];
    const float* b_oo   = (const float*)d_in[6];
    const float* W_ia   = (const float*)d_in[7];
    const float* b_ia   = (const float*)d_in[8];
    const float* W_is   = (const float*)d_in[9];
    const float* b_is   = (const float*)d_in[10];
    const float* W_gru  = (const float*)d_in[11];
    const float* ln_g   = (const float*)d_in[12];
    const float* ln_b   = (const float*)d_in[13];
    const float* W_od   = (const float*)d_in[14];
    const float* b_od   = (const float*)d_in[15];
    const float* W_op   = (const float*)d_in[16];
    const float* b_op   = (const float*)d_in[17];
    const float* W_io   = (const float*)d_in[18];
    const float* b_io   = (const float*)d_in[19];
    const float* W_ip   = (const float*)d_in[20];
    const float* b_ip   = (const float*)d_in[21];

    float* out    = (float*)d_out;
    float* deters = out;
    float* stochs = deters + (size_t)T_STEPS * B_SZ * D_;
    float* posts  = stochs + (size_t)T_STEPS * B_SZ * S_;
    float* priors = posts  + (size_t)T_STEPS * B_SZ * S_;

    float *obs_e, *act_e, *xbuf, *parts, *hbuf, *deter; int* idxb;
    cudaGetSymbolAddress((void**)&obs_e, g_obs_e);
    cudaGetSymbolAddress((void**)&act_e, g_act_e);
    cudaGetSymbolAddress((void**)&xbuf,  g_x);
    cudaGetSymbolAddress((void**)&parts, g_parts);
    cudaGetSymbolAddress((void**)&hbuf,  g_h);
    cudaGetSymbolAddress((void**)&deter, g_deter);
    cudaGetSymbolAddress((void**)&idxb,  g_idx);

    cudaMemcpyAsync(deter, deter0, (size_t)B_SZ * D_ * sizeof(float),
                    cudaMemcpyDeviceToDevice, 0);

    // obs_e = obs @ W_oo + b_oo
    launch_sgemm3<128,128,16,8,8,false,1>(obs, nullptr, W_oo, obs_e, b_oo, nullptr,
                                          T_STEPS * B_SZ, H_, OBS_, 0);
    // act_e = act @ W_ia + b_ia
    launch_sgemm3<128,128,16,8,8,false,1>(act, nullptr, W_ia, act_e, b_ia, nullptr,
                                          T_STEPS * B_SZ, H_, ACT_, 0);

    for (int t = 0; t < T_STEPS; ++t) {
        const float* ae = act_e + (size_t)t * B_SZ * H_;
        const float* oe = obs_e + (size_t)t * B_SZ * H_;

        // x = elu(act_e[t] + stoch @ W_is + b_is)
        if (t == 0) {
            launch_sgemm3<64,128,16,4,8,false,3>(stoch0, nullptr, W_is, xbuf, b_is, ae,
                                                 B_SZ, H_, S_, 0);
        } else {
            dim3 g(H_ / 256, B_SZ);
            x_gather_kernel<<<g, 256>>>(ae, b_is, W_is, idxb, xbuf);
        }
        // parts = [x | deter] @ W_gru
        launch_sgemm3<128,128,16,8,8,true,0>(xbuf, deter, W_gru, parts, nullptr, nullptr,
                                             B_SZ, 3 * D_, H_ + D_, H_);
        // layernorm + gates + deter update
        ln_gru_kernel<<<B_SZ, 256>>>(parts, ln_g, ln_b, deter,
                                     deters + (size_t)t * B_SZ * D_);
        // h = elu(deter @ W_od + b_od + obs_e[t])
        launch_sgemm3<64,128,16,4,8,false,3>(deter, nullptr, W_od, hbuf, b_od, oe,
                                             B_SZ, H_, D_, 0);
        // posts[t] = h @ W_op + b_op
        launch_sgemm3<64,64,16,4,4,false,1>(hbuf, nullptr, W_op,
                                            posts + (size_t)t * B_SZ * S_, b_op, nullptr,
                                            B_SZ, S_, H_, 0);
        // gumbel-max sample
        sample_kernel<<<(B_SZ * K_ * 32) / 256, 256>>>(
            posts + (size_t)t * B_SZ * S_,
            unif + (size_t)t * B_SZ * K_ * V_,
            idxb,
            stochs + (size_t)t * B_SZ * S_);
    }

    // priors = (elu(deters @ W_io + b_io)) @ W_ip + b_ip
    launch_sgemm3<128,128,16,8,8,false,2>(deters, nullptr, W_io, act_e, b_io, nullptr,
                                          T_STEPS * B_SZ, H_, D_, 0);
    launch_sgemm3<128,128,16,8,8,false,1>(act_e, nullptr, W_ip, priors, b_ip, nullptr,
                                          T_STEPS * B_SZ, S_, H_, 0);
}

// round 4
// speedup vs baseline: 1.1684x; 1.0023x over previous
#include <cuda_runtime.h>
#include <math.h>
#include <stdint.h>

// ---------------- problem constants ----------------
#define T_STEPS 64
#define B_SZ    512
#define OBS_    1536
#define ACT_    32
#define D_      2048
#define H_      2048
#define K_      32
#define V_      32
#define S_      1024   // K_*V_

// ---------------- device scratch ----------------
__device__ float g_obs_e[(size_t)T_STEPS * B_SZ * H_];
__device__ float g_act_e[(size_t)T_STEPS * B_SZ * H_];
__device__ float g_x[(size_t)B_SZ * H_];
__device__ float g_parts[(size_t)B_SZ * 3 * D_];
__device__ float g_h[(size_t)B_SZ * H_];
__device__ float g_deter[(size_t)B_SZ * D_];
__device__ int   g_idx[B_SZ * K_];

// ---------------- helpers ----------------
__device__ __forceinline__ void cp_async16(void* smem_dst, const void* gmem_src) {
    unsigned s = (unsigned)__cvta_generic_to_shared(smem_dst);
    asm volatile("cp.async.ca.shared.global [%0], [%1], 16;\n" :: "r"(s), "l"(gmem_src));
}
__device__ __forceinline__ void cp_async_commit() {
    asm volatile("cp.async.commit_group;\n" ::: "memory");
}
__device__ __forceinline__ void cp_async_wait_all() {
    asm volatile("cp.async.wait_group 0;\n" ::: "memory");
}
__device__ __forceinline__ void ffma2(unsigned long long& acc,
                                      unsigned long long a,
                                      unsigned long long b) {
    asm volatile("fma.rn.f32x2 %0, %1, %2, %0;\n" : "+l"(acc) : "l"(a), "l"(b));
}
__device__ __forceinline__ unsigned long long dup_f32(float b) {
    unsigned long long u;
    asm("mov.b64 %0, {%1, %1};\n" : "=l"(u) : "f"(b));
    return u;
}
__device__ __forceinline__ float2 ull2f2(unsigned long long v) {
    float2 r;
    r.x = __uint_as_float((unsigned)(v & 0xffffffffull));
    r.y = __uint_as_float((unsigned)(v >> 32));
    return r;
}

// ---------------- fp32 SGEMM: f32x2 FMA with M-paired A (no smem duplication) -------
// A operand pairs come straight out of LDS.128 of As[k][m] (consecutive m).
// B operand duplicated {b,b} in registers via mov.b64 (alu pipe).
// EPI: 0=none, 1=+bias, 2=+bias,ELU, 3=+bias,+addmat,ELU
template<int BM, int BN, int BK, int TM, int TN, bool CONCAT, int EPI>
__global__ void __launch_bounds__(256, 2)
sgemm3_kernel(const float* __restrict__ A, const float* __restrict__ A2,
              const float* __restrict__ B, float* __restrict__ C,
              const float* __restrict__ bias, const float* __restrict__ addm,
              int M, int N, int K, int K1)
{
    constexpr int THREADS = (BM/TM)*(BN/TN);
    static_assert(THREADS == 256, "expect 256 threads");
    static_assert(TM % 4 == 0 || TM == 4, "TM multiple of 4");
    constexpr int AROW = BM + 4;             // 16B-aligned row stride
    extern __shared__ __align__(16) float smem[];
    float* As = smem;                        // [2][BK][AROW]
    float* Bs = smem + 2*BK*AROW;            // [2][BK][BN]

    const int tid = threadIdx.x;
    const int tx  = tid % (BN/TN);
    const int ty  = tid / (BN/TN);
    const int bm  = blockIdx.y * BM;
    const int bn  = blockIdx.x * BN;

    constexpr int A_TPR = BK / 4;            // threads per A row (float4 along K)
    constexpr int A_RS  = THREADS / A_TPR;
    constexpr int A_IT  = BM / A_RS;
    const int a_r = tid / A_TPR;
    const int a_c = (tid % A_TPR) * 4;

    constexpr int B_TPR = BN / 4;
    constexpr int B_RS  = THREADS / B_TPR;
    constexpr int B_IT  = BK / B_RS;
    const int b_r = tid / B_TPR;
    const int b_c = (tid % B_TPR) * 4;

    float4 ar[A_IT];

    unsigned long long acc[TM/2][TN];        // pair along M: {row 2i, row 2i+1}
    #pragma unroll
    for (int i = 0; i < TM/2; ++i)
        #pragma unroll
        for (int j = 0; j < TN; ++j) acc[i][j] = 0ull;

    auto a_gload = [&](int kt) {
        const int k0 = kt * BK;
        #pragma unroll
        for (int i = 0; i < A_IT; ++i) {
            int gr = bm + a_r + i * A_RS;
            int gk = k0 + a_c;
            const float* src;
            if (CONCAT) {
                src = (gk < K1) ? (A  + (size_t)gr * K1       + gk)
                                : (A2 + (size_t)gr * (K - K1) + (gk - K1));
            } else {
                src = A + (size_t)gr * K + gk;
            }
            ar[i] = *(const float4*)src;
        }
    };
    auto a_sstore = [&](int bf) {
        float* base = As + (size_t)bf * BK * AROW;
        #pragma unroll
        for (int i = 0; i < A_IT; ++i) {
            int r = a_r + i * A_RS;
            base[(a_c + 0) * AROW + r] = ar[i].x;
            base[(a_c + 1) * AROW + r] = ar[i].y;
            base[(a_c + 2) * AROW + r] = ar[i].z;
            base[(a_c + 3) * AROW + r] = ar[i].w;
        }
    };
    auto b_gload = [&](int kt, int bf) {
        const int k0 = kt * BK;
        float* base = Bs + (size_t)bf * BK * BN;
        #pragma unroll
        for (int i = 0; i < B_IT; ++i) {
            int r = b_r + i * B_RS;
            cp_async16(base + r * BN + b_c, B + (size_t)(k0 + r) * N + bn + b_c);
        }
        cp_async_commit();
    };

    const int ntiles = K / BK;
    b_gload(0, 0);
    a_gload(0);
    a_sstore(0);
    cp_async_wait_all();
    __syncthreads();

    int buf = 0;
    for (int kt = 0; kt < ntiles; ++kt) {
        if (kt + 1 < ntiles) {
            b_gload(kt + 1, buf ^ 1);
            a_gload(kt + 1);
        }
        const float* Asb = As + (size_t)buf * BK * AROW;
        const float* Bsb = Bs + (size_t)buf * BK * BN;
        #pragma unroll
        for (int kk = 0; kk < BK; ++kk) {
            // A: LDS.128 -> two natural M-pairs each
            unsigned long long apair[TM/2];
            #pragma unroll
            for (int i4 = 0; i4 < TM/4; ++i4) {
                ulonglong2 p = *(const ulonglong2*)(Asb + kk * AROW + ty * TM + 4 * i4);
                apair[2*i4]     = p.x;
                apair[2*i4 + 1] = p.y;
            }
            // B: LDS.128 scalar, duplicate in registers (alu pipe)
            unsigned long long bdup[TN];
            #pragma unroll
            for (int j4 = 0; j4 < TN/4; ++j4) {
                float4 bv = *(const float4*)(Bsb + kk * BN + tx * TN + 4 * j4);
                bdup[4*j4 + 0] = dup_f32(bv.x);
                bdup[4*j4 + 1] = dup_f32(bv.y);
                bdup[4*j4 + 2] = dup_f32(bv.z);
                bdup[4*j4 + 3] = dup_f32(bv.w);
            }
            #pragma unroll
            for (int i = 0; i < TM/2; ++i)
                #pragma unroll
                for (int j = 0; j < TN; ++j)
                    ffma2(acc[i][j], apair[i], bdup[j]);
        }
        if (kt + 1 < ntiles) {
            a_sstore(buf ^ 1);
            cp_async_wait_all();
        }
        __syncthreads();
        buf ^= 1;
    }

    // epilogue: reassemble per-row vectors, vectorized float4 stores
    #pragma unroll
    for (int i2 = 0; i2 < TM/2; ++i2) {
        int row0 = bm + ty * TM + 2 * i2;
        float lo[TN], hi[TN];
        #pragma unroll
        for (int j = 0; j < TN; ++j) {
            float2 v = ull2f2(acc[i2][j]);
            lo[j] = v.x; hi[j] = v.y;
        }
        #pragma unroll
        for (int half = 0; half < 2; ++half) {
            int row = row0 + half;
            float* vals = half ? hi : lo;
            #pragma unroll
            for (int j = 0; j < TN; ++j) {
                int col = bn + tx * TN + j;
                float v = vals[j];
                if (EPI >= 1) v += bias[col];
                if (EPI == 3) v += addm[(size_t)row * N + col];
                if (EPI >= 2) v = (v > 0.f) ? v : expm1f(v);
                vals[j] = v;
            }
            #pragma unroll
            for (int j4 = 0; j4 < TN/4; ++j4)
                *(float4*)(C + (size_t)row * N + bn + tx * TN + 4 * j4) =
                    *(const float4*)(vals + 4 * j4);
        }
    }
}

// ---------------- x = elu(act_e[t] + b_is + sum of one-hot-selected W_is rows) -----
__global__ void x_gather_kernel(const float* __restrict__ ae,
                                const float* __restrict__ b_is,
                                const float* __restrict__ W_is,
                                const int* __restrict__ idx,
                                float* __restrict__ x)
{
    int j = blockIdx.x * blockDim.x + threadIdx.x;
    int b = blockIdx.y;
    __shared__ int sid[K_];
    if (threadIdx.x < K_) sid[threadIdx.x] = idx[b * K_ + threadIdx.x];
    __syncthreads();
    float v = ae[(size_t)b * H_ + j] + b_is[j];
    #pragma unroll
    for (int k = 0; k < K_; ++k)
        v += W_is[(size_t)sid[k] * H_ + j];
    x[(size_t)b * H_ + j] = (v > 0.f) ? v : expm1f(v);
}

// ---------------- fused LayerNorm(6144) + GRU gates + deter update ----------------
__global__ void ln_gru_kernel(const float* __restrict__ parts,
                              const float* __restrict__ ln_g,
                              const float* __restrict__ ln_b,
                              float* __restrict__ deter,
                              float* __restrict__ deters_out)
{
    const int row = blockIdx.x;
    const float* p = parts + (size_t)row * (3 * D_);
    float s = 0.f, s2 = 0.f;
    for (int i = threadIdx.x * 4; i < 3 * D_; i += 256 * 4) {
        float4 v = *(const float4*)(p + i);
        s  += v.x + v.y + v.z + v.w;
        s2 += v.x * v.x + v.y * v.y + v.z * v.z + v.w * v.w;
    }
    __shared__ float shs[8], shs2[8];
    #pragma unroll
    for (int off = 16; off > 0; off >>= 1) {
        s  += __shfl_down_sync(0xffffffffu, s,  off);
        s2 += __shfl_down_sync(0xffffffffu, s2, off);
    }
    int warp = threadIdx.x >> 5, lane = threadIdx.x & 31;
    if (lane == 0) { shs[warp] = s; shs2[warp] = s2; }
    __syncthreads();
    __shared__ float sh_m, sh_rstd;
    if (threadIdx.x == 0) {
        float S = 0.f, S2 = 0.f;
        #pragma unroll
        for (int i = 0; i < 8; ++i) { S += shs[i]; S2 += shs2[i]; }
        float m   = S * (1.f / (3 * D_));
        float var = S2 * (1.f / (3 * D_)) - m * m;
        sh_m = m; sh_rstd = rsqrtf(var + 1e-5f);
    }
    __syncthreads();
    const float m = sh_m, rstd = sh_rstd;
    for (int j = threadIdx.x; j < D_; j += 256) {
        float r = (p[j]          - m) * rstd * ln_g[j]          + ln_b[j];
        float c = (p[j + D_]     - m) * rstd * ln_g[j + D_]     + ln_b[j + D_];
        float u = (p[j + 2 * D_] - m) * rstd * ln_g[j + 2 * D_] + ln_b[j + 2 * D_];
        float sr   = 1.f / (1.f + expf(-r));
        float cand = tanhf(sr * c);
        float up   = 1.f / (1.f + expf(-(u - 1.f)));
        float dprev = deter[(size_t)row * D_ + j];
        float dn = up * cand + (1.f - up) * dprev;
        deter[(size_t)row * D_ + j] = dn;
        deters_out[(size_t)row * D_ + j] = dn;
    }
}

// ---------------- gumbel-max sampling: one warp per (b,k) ----------------
__global__ void sample_kernel(const float* __restrict__ logits,
                              const float* __restrict__ unif,
                              int* __restrict__ idx_out,
                              float* __restrict__ stochs_out)
{
    int gw   = (blockIdx.x * blockDim.x + threadIdx.x) >> 5;
    int lane = threadIdx.x & 31;
    size_t base = (size_t)gw * V_ + lane;
    float logit = logits[base];
    float u = unif[base];
    u = fminf(fmaxf(u, 1e-5f), 1.0f - 1e-5f);
    float val = logit - logf(-logf(u));
    int idx = lane;
    #pragma unroll
    for (int off = 16; off > 0; off >>= 1) {
        float ov = __shfl_down_sync(0xffffffffu, val, off);
        int   oi = __shfl_down_sync(0xffffffffu, idx, off);
        if (ov > val || (ov == val && oi < idx)) { val = ov; idx = oi; }
    }
    idx = __shfl_sync(0xffffffffu, idx, 0);
    stochs_out[base] = (lane == idx) ? 1.0f : 0.0f;
    if (lane == 0) idx_out[gw] = ((gw & (K_ - 1)) << 5) | idx;
}

// ---------------- launch helper ----------------
template<int BM, int BN, int BK, int TM, int TN, bool CONCAT, int EPI>
static void launch_sgemm3(const float* A, const float* A2, const float* B, float* C,
                          const float* bias, const float* addm,
                          int M, int N, int K, int K1)
{
    constexpr int AROW = BM + 4;
    constexpr size_t SMEM = (size_t)(2*BK*AROW + 2*BK*BN) * sizeof(float);
    static bool attr_set = false;
    if (!attr_set) {
        cudaFuncSetAttribute((const void*)sgemm3_kernel<BM,BN,BK,TM,TN,CONCAT,EPI>,
                             cudaFuncAttributeMaxDynamicSharedMemorySize, (int)SMEM);
        attr_set = true;
    }
    dim3 g(N / BN, M / BM);
    sgemm3_kernel<BM,BN,BK,TM,TN,CONCAT,EPI><<<g, 256, SMEM>>>(
        A, A2, B, C, bias, addm, M, N, K, K1);
}

// ---------------- host orchestration ----------------
extern "C" void kernel_launch(void* const* d_in, const int* in_sizes, int n_in,
                              void* d_out, int out_size)
{
    (void)in_sizes; (void)n_in; (void)out_size;
    const float* obs    = (const float*)d_in[0];
    const float* act    = (const float*)d_in[1];
    const float* deter0 = (const float*)d_in[2];
    const float* stoch0 = (const float*)d_in[3];
    const float* unif   = (const float*)d_in[4];
    const float* W_oo   = (const float*)d_in[5];
    const float* b_oo   = (const float*)d_in[6];
    const float* W_ia   = (const float*)d_in[7];
    const float* b_ia   = (const float*)d_in[8];
    const float* W_is   = (const float*)d_in[9];
    const float* b_is   = (const float*)d_in[10];
    const float* W_gru  = (const float*)d_in[11];
    const float* ln_g   = (const float*)d_in[12];
    const float* ln_b   = (const float*)d_in[13];
    const float* W_od   = (const float*)d_in[14];
    const float* b_od   = (const float*)d_in[15];
    const float* W_op   = (const float*)d_in[16];
    const float* b_op   = (const float*)d_in[17];
    const float* W_io   = (const float*)d_in[18];
    const float* b_io   = (const float*)d_in[19];
    const float* W_ip   = (const float*)d_in[20];
    const float* b_ip   = (const float*)d_in[21];

    float* out    = (float*)d_out;
    float* deters = out;
    float* stochs = deters + (size_t)T_STEPS * B_SZ * D_;
    float* posts  = stochs + (size_t)T_STEPS * B_SZ * S_;
    float* priors = posts  + (size_t)T_STEPS * B_SZ * S_;

    float *obs_e, *act_e, *xbuf, *parts, *hbuf, *deter; int* idxb;
    cudaGetSymbolAddress((void**)&obs_e, g_obs_e);
    cudaGetSymbolAddress((void**)&act_e, g_act_e);
    cudaGetSymbolAddress((void**)&xbuf,  g_x);
    cudaGetSymbolAddress((void**)&parts, g_parts);
    cudaGetSymbolAddress((void**)&hbuf,  g_h);
    cudaGetSymbolAddress((void**)&deter, g_deter);
    cudaGetSymbolAddress((void**)&idxb,  g_idx);

    cudaMemcpyAsync(deter, deter0, (size_t)B_SZ * D_ * sizeof(float),
                    cudaMemcpyDeviceToDevice, 0);

    // obs_e = obs @ W_oo + b_oo
    launch_sgemm3<128,128,16,8,8,false,1>(obs, nullptr, W_oo, obs_e, b_oo, nullptr,
                                          T_STEPS * B_SZ, H_, OBS_, 0);
    // act_e = act @ W_ia + b_ia
    launch_sgemm3<128,128,16,8,8,false,1>(act, nullptr, W_ia, act_e, b_ia, nullptr,
                                          T_STEPS * B_SZ, H_, ACT_, 0);

    for (int t = 0; t < T_STEPS; ++t) {
        const float* ae = act_e + (size_t)t * B_SZ * H_;
        const float* oe = obs_e + (size_t)t * B_SZ * H_;

        // x = elu(act_e[t] + stoch @ W_is + b_is)
        if (t == 0) {
            launch_sgemm3<64,128,16,4,8,false,3>(stoch0, nullptr, W_is, xbuf, b_is, ae,
                                                 B_SZ, H_, S_, 0);
        } else {
            dim3 g(H_ / 256, B_SZ);
            x_gather_kernel<<<g, 256>>>(ae, b_is, W_is, idxb, xbuf);
        }
        // parts = [x | deter] @ W_gru
        launch_sgemm3<128,128,16,8,8,true,0>(xbuf, deter, W_gru, parts, nullptr, nullptr,
                                             B_SZ, 3 * D_, H_ + D_, H_);
        // layernorm + gates + deter update
        ln_gru_kernel<<<B_SZ, 256>>>(parts, ln_g, ln_b, deter,
                                     deters + (size_t)t * B_SZ * D_);
        // h = elu(deter @ W_od + b_od + obs_e[t])
        launch_sgemm3<64,128,16,4,8,false,3>(deter, nullptr, W_od, hbuf, b_od, oe,
                                             B_SZ, H_, D_, 0);
        // posts[t] = h @ W_op + b_op
        launch_sgemm3<64,64,16,4,4,false,1>(hbuf, nullptr, W_op,
                                            posts + (size_t)t * B_SZ * S_, b_op, nullptr,
                                            B_SZ, S_, H_, 0);
        // gumbel-max sample
        sample_kernel<<<(B_SZ * K_ * 32) / 256, 256>>>(
            posts + (size_t)t * B_SZ * S_,
            unif + (size_t)t * B_SZ * K_ * V_,
            idxb,
            stochs + (size_t)t * B_SZ * S_);
    }

    // priors = (elu(deters @ W_io + b_io)) @ W_ip + b_ip
    launch_sgemm3<128,128,16,8,8,false,2>(deters, nullptr, W_io, act_e, b_io, nullptr,
                                          T_STEPS * B_SZ, H_, D_, 0);
    launch_sgemm3<128,128,16,8,8,false,1>(act_e, nullptr, W_ip, priors, b_ip, nullptr,
                                          T_STEPS * B_SZ, S_, H_, 0);
}